// round 9
// baseline (speedup 1.0000x reference)
#include <cuda_runtime.h>
#include <cuda_fp16.h>
#include <cstdint>

// ---------------- problem constants ----------------
#define N_TOK   262144
#define TOPK    2
#define NSLOTS  (N_TOK * TOPK)     // 524288
#define D       128
#define NEXP    8
#define TS      128                // slots per tile
#define MAXTILES (NSLOTS / TS + NEXP)   // 4104

// ---------------- device scratch ----------------
__device__ uint4 g_whp[NEXP * 2048];             // W fp16, packed [e][out][k] (32KB/expert)
__device__ int   g_seg[NEXP + 1];
__device__ int   g_tile_e[MAXTILES];
__device__ int   g_tile_s[MAXTILES];
__device__ int   g_ntiles;

// ---------------- helpers ----------------
__device__ __forceinline__ uint32_t smem_u32(const void* p) {
    uint32_t a;
    asm("{ .reg .u64 t; cvta.to.shared.u64 t, %1; cvt.u32.u64 %0, t; }" : "=r"(a) : "l"(p));
    return a;
}
__device__ __forceinline__ void ldsm_x4(uint32_t* r, uint32_t addr) {
    asm volatile("ldmatrix.sync.aligned.m8n8.x4.shared.b16 {%0,%1,%2,%3}, [%4];"
        : "=r"(r[0]), "=r"(r[1]), "=r"(r[2]), "=r"(r[3]) : "r"(addr));
}
__device__ __forceinline__ void mma_fp16(float* c, const uint32_t* a, uint32_t b0, uint32_t b1) {
    asm volatile("mma.sync.aligned.m16n8k16.row.col.f32.f16.f16.f32 "
        "{%0,%1,%2,%3}, {%4,%5,%6,%7}, {%8,%9}, {%0,%1,%2,%3};"
        : "+f"(c[0]), "+f"(c[1]), "+f"(c[2]), "+f"(c[3])
        : "r"(a[0]), "r"(a[1]), "r"(a[2]), "r"(a[3]), "r"(b0), "r"(b1));
}
#define RED_ADD_V2(ptr, a, b) \
    asm volatile("red.global.add.v2.f32 [%0], {%1, %2};" :: "l"(ptr), "f"(a), "f"(b) : "memory")

// convert 8 fp32 -> fp16 (16 B)
__device__ __forceinline__ uint4 cvt8h(const float* v) {
    uint32_t hu[4];
#pragma unroll
    for (int i = 0; i < 4; i++) {
        __half2 hp = __floats2half2_rn(v[2 * i], v[2 * i + 1]);
        hu[i] = *reinterpret_cast<uint32_t*>(&hp);
    }
    return make_uint4(hu[0], hu[1], hu[2], hu[3]);
}

// -------------------------------------------------------------------
// Prologue 1: weight fp32 [E, d_out, d_in] -> packed fp16
// -------------------------------------------------------------------
__global__ void wconv_kernel(const float* __restrict__ w) {
    int e = blockIdx.x;
    int tid = threadIdx.x;
    int row = tid >> 1;
    int half = tid & 1;
    const float* wr = w + ((size_t)e * D + row) * D;
    uint4* whe = g_whp + e * 2048;
#pragma unroll
    for (int g = 0; g < 8; g++) {
        int col0 = half * 64 + g * 8;
        float v[8];
#pragma unroll
        for (int i = 0; i < 8; i++) v[i] = wr[col0 + i];
        whe[row * 16 + half * 8 + g] = cvt8h(v);
    }
}

// -------------------------------------------------------------------
// Prologue 2: expert segments + dense tile map
// -------------------------------------------------------------------
__global__ void seg_kernel(const int* __restrict__ sei) {
    __shared__ int seg[NEXP + 1];
    __shared__ int cnts[NEXP];
    int t = threadIdx.x;
    if (t <= NEXP) {
        int lo = 0, hi = NSLOTS;
        while (lo < hi) {
            int mid = (lo + hi) >> 1;
            if (sei[mid] < t) lo = mid + 1; else hi = mid;
        }
        seg[t] = lo;
        g_seg[t] = lo;
    }
    __syncthreads();
    if (t < NEXP) cnts[t] = (seg[t + 1] - seg[t] + TS - 1) / TS;
    __syncthreads();
    if (t < NEXP) {
        int off = 0;
        for (int i = 0; i < t; i++) off += cnts[i];
        int s = seg[t];
        for (int i = 0; i < cnts[t]; i++) {
            g_tile_e[off + i] = t;
            g_tile_s[off + i] = s + i * TS;
        }
    }
    if (t == 0) {
        int tot = 0;
        for (int i = 0; i < NEXP; i++) tot += cnts[i];
        g_ntiles = tot;
    }
}

// -------------------------------------------------------------------
// Prologue 3: zero-init out (atomic accumulation target)
// -------------------------------------------------------------------
__global__ void zero_kernel(float4* __restrict__ out) {
    size_t idx = (size_t)blockIdx.x * blockDim.x + threadIdx.x;
    out[idx] = make_float4(0.f, 0.f, 0.f, 0.f);
}

// -------------------------------------------------------------------
// SMEM layout: ping-pong X images + meta, single W image (104 KB)
// -------------------------------------------------------------------
#define XROWB 272
#define IMGB  (128 * XROWB)          // 34816
#define OFF_SHF 0                    // int [2][128]
#define OFF_SHG 1024                 // float [2][128]
#define OFF_X0  2048
#define OFF_X1  (OFF_X0 + IMGB)      // 36864
#define OFF_WH  (OFF_X1 + IMGB)      // 71680
#define SMEM_TOTAL (OFF_WH + IMGB)   // 106496

// -------------------------------------------------------------------
// Main: persistent fp16 HMMA, ping-pong pipeline, 1 barrier/tile
// -------------------------------------------------------------------
extern "C" __global__ void __launch_bounds__(256, 2)
moe_mma_kernel(const float* __restrict__ x,
               const float* __restrict__ gates,
               const int*   __restrict__ ssi,
               float* __restrict__ out) {
    int ntiles = g_ntiles;
    int nc = gridDim.x;
    int per = ntiles / nc, rem = ntiles % nc;
    int t0 = blockIdx.x * per + min((int)blockIdx.x, rem);
    int t1 = t0 + per + (blockIdx.x < rem ? 1 : 0);
    if (t0 >= t1) return;

    extern __shared__ char smem[];
    uint32_t sb = smem_u32(smem);
    int*   sh_f = (int*)(smem + OFF_SHF);    // [2][128]
    float* sh_g = (float*)(smem + OFF_SHG);  // [2][128]

    int tid = threadIdx.x;
    int wid = tid >> 5;
    int lane = tid & 31;
    int r = tid >> 1;                 // staging row (2 threads per row)
    int half = tid & 1;

    // warp tiles: wr 0..3 (32 slots), wc 0..1 (64 outs)
    int wr = wid & 3;
    int wc = wid >> 2;
    int lrow = (lane & 7) | (lane & 8);
    int kby  = (lane >> 4) * 16;
    uint32_t aA0 = sb + OFF_X0 + (uint32_t)(wr * 32 + lrow) * XROWB + kby;
    uint32_t aB  = sb + OFF_WH + (uint32_t)(wc * 64 + lrow) * XROWB + kby;

    const float4* x4 = (const float4*)x;

    // ---- prime tile t0: meta + image buf0 ----
    int ecur = g_tile_e[t0];
    {
        int s0 = g_tile_s[t0];
        int c0 = min(TS, g_seg[ecur + 1] - s0);
        int   f0 = (r < c0) ? ssi[s0 + r] : 0;
        float g0 = (r < c0) ? gates[f0] : 0.f;
        const float4* xp = x4 + (size_t)(f0 >> 1) * 32 + half * 16;
        char* xi = smem + OFF_X0;
#pragma unroll
        for (int g = 0; g < 8; g++) {
            float4 a = xp[g * 2];
            float4 b = xp[g * 2 + 1];
            float v[8] = {a.x, a.y, a.z, a.w, b.x, b.y, b.z, b.w};
            *(uint4*)(xi + (uint32_t)r * XROWB + (half * 64 + g * 8) * 2) = cvt8h(v);
        }
        if (!half) { sh_f[r] = f0; sh_g[r] = g0; }
    }
    int cntcur;
    {
        int s0 = g_tile_s[t0];
        cntcur = min(TS, g_seg[ecur + 1] - s0);
    }

    // ---- prefetch meta for t0+1 ----
    int e1 = ecur, cnt1 = 0, f1 = 0; float gg1 = 0.f;
    if (t0 + 1 < t1) {
        e1 = g_tile_e[t0 + 1];
        int s1 = g_tile_s[t0 + 1];
        cnt1 = min(TS, g_seg[e1 + 1] - s1);
        f1 = (r < cnt1) ? ssi[s1 + r] : 0;
        gg1 = (r < cnt1) ? gates[f1] : 0.f;
    }
    __syncthreads();

    int staged_e = -1;

    for (int t = t0; t < t1; t++) {
        int buf = (t - t0) & 1;
        bool have1 = (t + 1 < t1);
        bool have2 = (t + 2 < t1);

        // ---- issue gather LDGs for t+1 (covered by MMA below) ----
        float4 xr[8];
        const float4* xp1 = x4 + (size_t)(f1 >> 1) * 32 + half * 16;
        if (have1) {
#pragma unroll
            for (int g = 0; g < 8; g++) xr[g] = xp1[g * 2];
        }

        // ---- prefetch meta for t+2 ----
        int e2 = e1, cnt2 = 0, f2 = 0; float gg2 = 0.f;
        if (have2) {
            e2 = g_tile_e[t + 2];
            int s2 = g_tile_s[t + 2];
            cnt2 = min(TS, g_seg[e2 + 1] - s2);
            f2 = (r < cnt2) ? ssi[s2 + r] : 0;
            gg2 = (r < cnt2) ? gates[f2] : 0.f;
        }

        // ---- stage W on expert change (rare; needs extra barrier) ----
        if (ecur != staged_e) {
            const uint4* whe = g_whp + ecur * 2048;
#pragma unroll
            for (int i = 0; i < 8; i++) {
                int cid = tid + 256 * i;
                int row = cid >> 4;
                int w16 = cid & 15;
                *(uint4*)(smem + OFF_WH + row * XROWB + w16 * 16) = whe[cid];
            }
            staged_e = ecur;
            __syncthreads();
        }

        // ---- MMA from image[buf] ----
        uint32_t aA = aA0 + (uint32_t)buf * IMGB;
        float acc[2][8][4];
#pragma unroll
        for (int mt = 0; mt < 2; mt++)
#pragma unroll
            for (int nt = 0; nt < 8; nt++)
#pragma unroll
                for (int i = 0; i < 4; i++) acc[mt][nt][i] = 0.f;

#pragma unroll
        for (int kk = 0; kk < 8; kk++) {
            uint32_t kb = kk * 32;
            uint32_t ah[2][4];
            ldsm_x4(ah[0], aA + kb);
            ldsm_x4(ah[1], aA + 16 * XROWB + kb);
#pragma unroll
            for (int ng = 0; ng < 4; ng++) {
                uint32_t bh[4];
                ldsm_x4(bh, aB + ng * 16 * XROWB + kb);
#pragma unroll
                for (int mt = 0; mt < 2; mt++) {
                    mma_fp16(acc[mt][2 * ng],     ah[mt], bh[0], bh[2]);
                    mma_fp16(acc[mt][2 * ng + 1], ah[mt], bh[1], bh[3]);
                }
            }
        }

        // ---- fused epilogue: gate + atomic-add into out ----
        {
            int row_lo = lane >> 2;
            int col0 = wc * 64 + (lane & 3) * 2;
            const int*   fb = sh_f + buf * 128;
            const float* gb = sh_g + buf * 128;
#pragma unroll
            for (int mt = 0; mt < 2; mt++) {
                int ja = wr * 32 + mt * 16 + row_lo;
                int jb = ja + 8;
                bool oka = ja < cntcur, okb = jb < cntcur;
                float ga = gb[ja], gbv = gb[jb];
                float* da = out + (size_t)(fb[ja] >> 1) * D + col0;
                float* db = out + (size_t)(fb[jb] >> 1) * D + col0;
#pragma unroll
                for (int nt = 0; nt < 8; nt++) {
                    if (oka)
                        RED_ADD_V2(da + nt * 8, acc[mt][nt][0] * ga, acc[mt][nt][1] * ga);
                    if (okb)
                        RED_ADD_V2(db + nt * 8, acc[mt][nt][2] * gbv, acc[mt][nt][3] * gbv);
                }
            }
        }

        // ---- convert t+1 into image[buf^1] + meta[buf^1] ----
        if (have1) {
            char* xi = smem + (buf ? OFF_X0 : OFF_X1);
#pragma unroll
            for (int g = 0; g < 8; g++) {
                float4 a = xr[g];
                float4 b = xp1[g * 2 + 1];     // same 32B sector as xr[g] -> L1 hit
                float v[8] = {a.x, a.y, a.z, a.w, b.x, b.y, b.z, b.w};
                *(uint4*)(xi + (uint32_t)r * XROWB + (half * 64 + g * 8) * 2) = cvt8h(v);
            }
            if (!half) {
                sh_f[(buf ^ 1) * 128 + r] = f1;
                sh_g[(buf ^ 1) * 128 + r] = gg1;
            }
        }
        __syncthreads();

        // rotate pipeline state
        ecur = e1; cntcur = cnt1;
        e1 = e2; cnt1 = cnt2; f1 = f2; gg1 = gg2;
    }
}

// -------------------------------------------------------------------
extern "C" void kernel_launch(void* const* d_in, const int* in_sizes, int n_in,
                              void* d_out, int out_size) {
    const float* inputs = (const float*)d_in[0];
    const float* weight = (const float*)d_in[1];
    const float* gates  = (const float*)d_in[2];
    const int*   sei    = (const int*)d_in[4];
    const int*   ssi    = (const int*)d_in[5];
    float* out = (float*)d_out;

    int nsm = 148;
    cudaDeviceGetAttribute(&nsm, cudaDevAttrMultiProcessorCount, 0);

    cudaFuncSetAttribute(moe_mma_kernel,
                         cudaFuncAttributeMaxDynamicSharedMemorySize, SMEM_TOTAL);

    wconv_kernel<<<NEXP, 256>>>(weight);
    seg_kernel<<<1, 32>>>(sei);
    zero_kernel<<<(N_TOK * D / 4) / 256, 256>>>((float4*)out);

    moe_mma_kernel<<<2 * nsm, 256, SMEM_TOTAL>>>(inputs, gates, ssi, out);
}

// round 10
// speedup vs baseline: 1.1774x; 1.1774x over previous
#include <cuda_runtime.h>
#include <cuda_fp16.h>
#include <cstdint>

// ---------------- problem constants ----------------
#define N_TOK   262144
#define TOPK    2
#define NSLOTS  (N_TOK * TOPK)     // 524288
#define D       128
#define NEXP    8
#define TS      64                 // slots per tile
#define NTHR    128                // threads per CTA (4 warps)
#define MAXTILES (NSLOTS / TS + NEXP)   // 8200

// ---------------- device scratch ----------------
__device__ uint4 g_whp[NEXP * 2048];             // W fp16, packed [e][out][k] (32KB/expert)
__device__ int   g_seg[NEXP + 1];
__device__ int   g_tile_e[MAXTILES];
__device__ int   g_tile_s[MAXTILES];
__device__ int   g_ntiles;

// ---------------- helpers ----------------
__device__ __forceinline__ uint32_t smem_u32(const void* p) {
    uint32_t a;
    asm("{ .reg .u64 t; cvta.to.shared.u64 t, %1; cvt.u32.u64 %0, t; }" : "=r"(a) : "l"(p));
    return a;
}
__device__ __forceinline__ void ldsm_x4(uint32_t* r, uint32_t addr) {
    asm volatile("ldmatrix.sync.aligned.m8n8.x4.shared.b16 {%0,%1,%2,%3}, [%4];"
        : "=r"(r[0]), "=r"(r[1]), "=r"(r[2]), "=r"(r[3]) : "r"(addr));
}
__device__ __forceinline__ void mma_fp16(float* c, const uint32_t* a, uint32_t b0, uint32_t b1) {
    asm volatile("mma.sync.aligned.m16n8k16.row.col.f32.f16.f16.f32 "
        "{%0,%1,%2,%3}, {%4,%5,%6,%7}, {%8,%9}, {%0,%1,%2,%3};"
        : "+f"(c[0]), "+f"(c[1]), "+f"(c[2]), "+f"(c[3])
        : "r"(a[0]), "r"(a[1]), "r"(a[2]), "r"(a[3]), "r"(b0), "r"(b1));
}
#define RED_ADD_V2(ptr, a, b) \
    asm volatile("red.global.add.v2.f32 [%0], {%1, %2};" :: "l"(ptr), "f"(a), "f"(b) : "memory")
#define PREFETCH_L2(ptr) \
    asm volatile("prefetch.global.L2 [%0];" :: "l"(ptr))

// convert 8 fp32 -> fp16 (16 B)
__device__ __forceinline__ uint4 cvt8h(const float* v) {
    uint32_t hu[4];
#pragma unroll
    for (int i = 0; i < 4; i++) {
        __half2 hp = __floats2half2_rn(v[2 * i], v[2 * i + 1]);
        hu[i] = *reinterpret_cast<uint32_t*>(&hp);
    }
    return make_uint4(hu[0], hu[1], hu[2], hu[3]);
}

// -------------------------------------------------------------------
// Prologue 1: weight fp32 [E, d_out, d_in] -> packed fp16
// -------------------------------------------------------------------
__global__ void wconv_kernel(const float* __restrict__ w) {
    int e = blockIdx.x;
    int tid = threadIdx.x;
    int row = tid >> 1;
    int half = tid & 1;
    const float* wr = w + ((size_t)e * D + row) * D;
    uint4* whe = g_whp + e * 2048;
#pragma unroll
    for (int g = 0; g < 8; g++) {
        int col0 = half * 64 + g * 8;
        float v[8];
#pragma unroll
        for (int i = 0; i < 8; i++) v[i] = wr[col0 + i];
        whe[row * 16 + half * 8 + g] = cvt8h(v);
    }
}

// -------------------------------------------------------------------
// Prologue 2: expert segments + dense tile map
// -------------------------------------------------------------------
__global__ void seg_kernel(const int* __restrict__ sei) {
    __shared__ int seg[NEXP + 1];
    __shared__ int cnts[NEXP];
    int t = threadIdx.x;
    if (t <= NEXP) {
        int lo = 0, hi = NSLOTS;
        while (lo < hi) {
            int mid = (lo + hi) >> 1;
            if (sei[mid] < t) lo = mid + 1; else hi = mid;
        }
        seg[t] = lo;
        g_seg[t] = lo;
    }
    __syncthreads();
    if (t < NEXP) cnts[t] = (seg[t + 1] - seg[t] + TS - 1) / TS;
    __syncthreads();
    if (t < NEXP) {
        int off = 0;
        for (int i = 0; i < t; i++) off += cnts[i];
        int s = seg[t];
        for (int i = 0; i < cnts[t]; i++) {
            g_tile_e[off + i] = t;
            g_tile_s[off + i] = s + i * TS;
        }
    }
    if (t == 0) {
        int tot = 0;
        for (int i = 0; i < NEXP; i++) tot += cnts[i];
        g_ntiles = tot;
    }
}

// -------------------------------------------------------------------
// Prologue 3: zero-init out (atomic accumulation target)
// -------------------------------------------------------------------
__global__ void zero_kernel(float4* __restrict__ out) {
    size_t idx = (size_t)blockIdx.x * blockDim.x + threadIdx.x;
    out[idx] = make_float4(0.f, 0.f, 0.f, 0.f);
}

// -------------------------------------------------------------------
// SMEM layout (52 KB -> 4 CTAs/SM)
// -------------------------------------------------------------------
#define XROWB 272
#define XIMGB (TS * XROWB)           // 17408
#define WIMGB (128 * XROWB)          // 34816
#define OFF_SHF 0                    // int [64]
#define OFF_SHG 256                  // float [64]
#define OFF_XH  512
#define OFF_WH  (OFF_XH + XIMGB)     // 17920
#define SMEM_TOTAL (OFF_WH + WIMGB)  // 52736

// -------------------------------------------------------------------
// Main: persistent fp16 HMMA, TS=64, 4 CTAs/SM, L2-prefetched gather
// -------------------------------------------------------------------
extern "C" __global__ void __launch_bounds__(NTHR, 4)
moe_mma_kernel(const float* __restrict__ x,
               const float* __restrict__ gates,
               const int*   __restrict__ ssi,
               float* __restrict__ out) {
    int ntiles = g_ntiles;
    int nc = gridDim.x;
    int per = ntiles / nc, rem = ntiles % nc;
    int t0 = blockIdx.x * per + min((int)blockIdx.x, rem);
    int t1 = t0 + per + (blockIdx.x < rem ? 1 : 0);
    if (t0 >= t1) return;

    extern __shared__ char smem[];
    uint32_t sb = smem_u32(smem);
    int*   sh_f = (int*)(smem + OFF_SHF);
    float* sh_g = (float*)(smem + OFF_SHG);

    int tid = threadIdx.x;
    int wid = tid >> 5;
    int lane = tid & 31;
    int r = tid >> 1;                 // staging row (2 threads per row, 64 rows)
    int half = tid & 1;

    // warp tiles: wr 0..1 (32 slots), wc 0..1 (64 outs)
    int wr = wid & 1;
    int wc = wid >> 1;
    int lrow = (lane & 7) | (lane & 8);
    int kby  = (lane >> 4) * 16;
    uint32_t aA = sb + OFF_XH + (uint32_t)(wr * 32 + lrow) * XROWB + kby;
    uint32_t aB = sb + OFF_WH + (uint32_t)(wc * 64 + lrow) * XROWB + kby;

    // ---- prime tile t0 metadata ----
    int e  = g_tile_e[t0];
    int s0 = g_tile_s[t0];
    int cnt = min(TS, g_seg[e + 1] - s0);
    int   fcur = (r < cnt) ? ssi[s0 + r] : 0;
    float gcur = (r < cnt) ? gates[fcur] : 0.f;

    int staged_e = -1;

    for (int t = t0; t < t1; t++) {
        // ---- issue X gather for this tile (L2-prefetched last iter) ----
        float4 xr[8];
        const float4* xp = (const float4*)x + (size_t)(fcur >> 1) * 32 + half * 16;
#pragma unroll
        for (int g = 0; g < 8; g++) xr[g] = xp[g * 2];

        // ---- prefetch metadata for t+1 + L2-prefetch its X rows ----
        bool havenext = (t + 1 < t1);
        int en = e, s0n = s0, cntn = cnt, fnxt = 0; float gnxt = 0.f;
        if (havenext) {
            en  = g_tile_e[t + 1];
            s0n = g_tile_s[t + 1];
            cntn = min(TS, g_seg[en + 1] - s0n);
            fnxt = (r < cntn) ? ssi[s0n + r] : 0;
            gnxt = (r < cntn) ? gates[fnxt] : 0.f;
            const char* pf = (const char*)x + (size_t)(fnxt >> 1) * 512 + half * 256;
            PREFETCH_L2(pf);
            PREFETCH_L2(pf + 128);
        }

        __syncthreads();       // prev tile MMA/epilogue done -> safe to overwrite image

        // ---- stage W on expert change (rare) ----
        if (e != staged_e) {
            const uint4* whe = g_whp + e * 2048;
#pragma unroll
            for (int i = 0; i < 16; i++) {
                int cid = tid + NTHR * i;
                int row = cid >> 4;
                int w16 = cid & 15;
                *(uint4*)(smem + OFF_WH + row * XROWB + w16 * 16) = whe[cid];
            }
            staged_e = e;
        }

        // ---- metadata to smem ----
        if (!half) {
            sh_f[r] = fcur;
            sh_g[r] = gcur;
        }

        // ---- convert + STS fp16 image ----
        {
            char* xh = smem + OFF_XH;
#pragma unroll
            for (int g = 0; g < 8; g++) {
                float4 a = xr[g];
                float4 b = xp[g * 2 + 1];      // same 32B sector -> L1 hit
                float v[8] = {a.x, a.y, a.z, a.w, b.x, b.y, b.z, b.w};
                uint4 hv = cvt8h(v);
                *(uint4*)(xh + (uint32_t)r * XROWB + (half * 64 + g * 8) * 2) = hv;
            }
        }
        __syncthreads();       // image + meta ready

        // ---- MMA: single fp16 pass, warp 32x64 ----
        float acc[2][8][4];
#pragma unroll
        for (int mt = 0; mt < 2; mt++)
#pragma unroll
            for (int nt = 0; nt < 8; nt++)
#pragma unroll
                for (int i = 0; i < 4; i++) acc[mt][nt][i] = 0.f;

#pragma unroll
        for (int kk = 0; kk < 8; kk++) {
            uint32_t kb = kk * 32;
            uint32_t ah[2][4];
            ldsm_x4(ah[0], aA + kb);
            ldsm_x4(ah[1], aA + 16 * XROWB + kb);
#pragma unroll
            for (int ng = 0; ng < 4; ng++) {
                uint32_t bh[4];
                ldsm_x4(bh, aB + ng * 16 * XROWB + kb);
#pragma unroll
                for (int mt = 0; mt < 2; mt++) {
                    mma_fp16(acc[mt][2 * ng],     ah[mt], bh[0], bh[2]);
                    mma_fp16(acc[mt][2 * ng + 1], ah[mt], bh[1], bh[3]);
                }
            }
        }

        // ---- fused epilogue: gate + atomic-add into out ----
        // each out element receives exactly TOPK=2 adds -> order-independent
        {
            int row_lo = lane >> 2;
            int col0 = wc * 64 + (lane & 3) * 2;
#pragma unroll
            for (int mt = 0; mt < 2; mt++) {
                int ja = wr * 32 + mt * 16 + row_lo;
                int jb = ja + 8;
                bool oka = ja < cnt, okb = jb < cnt;
                float ga = sh_g[ja], gb = sh_g[jb];
                float* da = out + (size_t)(sh_f[ja] >> 1) * D + col0;
                float* db = out + (size_t)(sh_f[jb] >> 1) * D + col0;
#pragma unroll
                for (int nt = 0; nt < 8; nt++) {
                    if (oka)
                        RED_ADD_V2(da + nt * 8, acc[mt][nt][0] * ga, acc[mt][nt][1] * ga);
                    if (okb)
                        RED_ADD_V2(db + nt * 8, acc[mt][nt][2] * gb, acc[mt][nt][3] * gb);
                }
            }
        }

        // rotate tile state
        e = en; s0 = s0n; cnt = cntn; fcur = fnxt; gcur = gnxt;
    }
}

// -------------------------------------------------------------------
extern "C" void kernel_launch(void* const* d_in, const int* in_sizes, int n_in,
                              void* d_out, int out_size) {
    const float* inputs = (const float*)d_in[0];
    const float* weight = (const float*)d_in[1];
    const float* gates  = (const float*)d_in[2];
    const int*   sei    = (const int*)d_in[4];
    const int*   ssi    = (const int*)d_in[5];
    float* out = (float*)d_out;

    int nsm = 148;
    cudaDeviceGetAttribute(&nsm, cudaDevAttrMultiProcessorCount, 0);

    cudaFuncSetAttribute(moe_mma_kernel,
                         cudaFuncAttributeMaxDynamicSharedMemorySize, SMEM_TOTAL);

    wconv_kernel<<<NEXP, 256>>>(weight);
    seg_kernel<<<1, 32>>>(sei);
    zero_kernel<<<(N_TOK * D / 4) / 256, 256>>>((float4*)out);

    moe_mma_kernel<<<4 * nsm, NTHR, SMEM_TOTAL>>>(inputs, gates, ssi, out);
}